// round 10
// baseline (speedup 1.0000x reference)
#include <cuda_runtime.h>
#include <cuda_bf16.h>
#include <cstdint>

#define NEG 0.01f
__device__ __forceinline__ float lrelu(float v) { return v >= 0.f ? v : NEG * v; }

// ---- bf16 GEMM tile: CTA 64(M) x 128(N) x 64(K) per iter, 4-stage smem ring ----
#define XS_STRIDE 72            // bf16 (64 + 8 pad) -> 144B rows, LDSM conflict-free
#define WS_STRIDE 136           // bf16 (128 + 8 pad) -> 272B rows
#define XS_ELEMS (64 * XS_STRIDE)
#define WS_ELEMS (64 * WS_STRIDE)
#define STAGE_ELEMS (XS_ELEMS + WS_ELEMS)          // 13312 bf16 = 26624 B
#define NSTAGE 4
#define GEMM_SMEM_BYTES (NSTAGE * STAGE_ELEMS * 2) // 106496 B

// ---------------- scratch (device globals) ----------------
__device__ float g_Y1[64 * 3200];
__device__ float g_Y2[64 * 6400];
__device__ float g_Y3[64 * 12800];
__device__ __nv_bfloat16 g_Xin[64 * 25600];
__device__ __nv_bfloat16 g_Xb1[64 * 3200];
__device__ __nv_bfloat16 g_Xb2[64 * 6400];
__device__ __nv_bfloat16 g_Xb3[64 * 12800];
__device__ __nv_bfloat16 g_X2b[64 * 50 * 128];
__device__ float g_H [64 * 50 * 128];
__device__ float g_PL[64 * 128];

// ---------------- helpers ----------------
__device__ __forceinline__ uint32_t pack_bf16(float lo, float hi) {
    uint32_t r;
    asm("cvt.rn.bf16x2.f32 %0, %1, %2;" : "=r"(r) : "f"(hi), "f"(lo));
    return r;
}
__device__ __forceinline__ void cp16(void* dst_smem, const void* src) {
    uint32_t d = (uint32_t)__cvta_generic_to_shared(dst_smem);
    asm volatile("cp.async.cg.shared.global [%0], [%1], 16;\n" :: "r"(d), "l"(src));
}
__device__ __forceinline__ void cp_commit() { asm volatile("cp.async.commit_group;\n"); }
template<int NN> __device__ __forceinline__ void cp_wait() {
    asm volatile("cp.async.wait_group %0;\n" :: "n"(NN));
}
__device__ __forceinline__ void ldsm4(uint32_t* r, uint32_t addr) {
    asm volatile("ldmatrix.sync.aligned.m8n8.x4.shared.b16 {%0,%1,%2,%3}, [%4];"
                 : "=r"(r[0]), "=r"(r[1]), "=r"(r[2]), "=r"(r[3]) : "r"(addr));
}
__device__ __forceinline__ void ldsm4t(uint32_t* r, uint32_t addr) {
    asm volatile("ldmatrix.sync.aligned.m8n8.x4.trans.shared.b16 {%0,%1,%2,%3}, [%4];"
                 : "=r"(r[0]), "=r"(r[1]), "=r"(r[2]), "=r"(r[3]) : "r"(addr));
}
__device__ __forceinline__ void mma16816(float* c, const uint32_t* a, uint32_t b0, uint32_t b1) {
    asm("mma.sync.aligned.m16n8k16.row.col.f32.bf16.bf16.f32 "
        "{%0,%1,%2,%3}, {%4,%5,%6,%7}, {%8,%9}, {%0,%1,%2,%3};"
        : "+f"(c[0]), "+f"(c[1]), "+f"(c[2]), "+f"(c[3])
        : "r"(a[0]), "r"(a[1]), "r"(a[2]), "r"(a[3]), "r"(b0), "r"(b1));
}

// ---------------- prep: bias-init Y1..Y3, convert input b -> bf16 ----------------
__global__ void prep_kernel(float4* __restrict__ Y1, const float4* __restrict__ B1,
                            float4* __restrict__ Y2, const float4* __restrict__ B2,
                            float4* __restrict__ Y3, const float4* __restrict__ B3,
                            const float4* __restrict__ bin, uint2* __restrict__ Xin) {
    int i = blockIdx.x * 256 + threadIdx.x;
    if (i < 51200)        Y1[i] = B1[i % 800];
    else if (i < 153600)  { int j = i - 51200;  Y2[j] = B2[j % 1600]; }
    else if (i < 358400)  { int j = i - 153600; Y3[j] = B3[j % 3200]; }
    else if (i < 768000)  {
        int j = i - 358400;
        float4 v = bin[j];
        Xin[j] = make_uint2(pack_bf16(v.x, v.y), pack_bf16(v.z, v.w));
    }
}

// ---------------- post pass: fp32 Y -> (leaky) -> bf16 X ----------------
__global__ void post_act(const float4* __restrict__ Y, uint2* __restrict__ Xb,
                         int n4, int leak) {
    int i = blockIdx.x * 256 + threadIdx.x;
    if (i < n4) {
        float4 v = Y[i];
        if (leak) { v.x = lrelu(v.x); v.y = lrelu(v.y); v.z = lrelu(v.z); v.w = lrelu(v.w); }
        Xb[i] = make_uint2(pack_bf16(v.x, v.y), pack_bf16(v.z, v.w));
    }
}

// ---------------- bf16 mma GEMM ----------------
// X bf16 via cp.async (4-stage ring, prefetch distance 3, 2 groups in flight);
// W fp32 LDG -> bf16 STS with 2 half-K register buffers: LDG->STS distance = 1 iter.
// grid: (N/128, numKChunks, M/64). direct=1: plain store (grid.y==1).
// K, chunkLen multiples of 64; N multiple of 128.
__global__ __launch_bounds__(256, 2) void gemm_bf16(
    const __nv_bfloat16* __restrict__ X, const float* __restrict__ W,
    float* __restrict__ Y, int K, int N, int chunkLen, int direct)
{
    extern __shared__ __align__(16) char smraw[];
    __nv_bfloat16* sm = reinterpret_cast<__nv_bfloat16*>(smraw);

    const int tid = threadIdx.x;
    const int warp = tid >> 5, lane = tid & 31;
    const int g = lane >> 2, t = lane & 3;

    const int n0 = blockIdx.x * 128;
    const int m0 = blockIdx.z * 64;
    const int k0 = blockIdx.y * chunkLen;
    int kend = k0 + chunkLen; if (kend > K) kend = K;
    const int iters = (kend - k0) >> 6;

    const int wm = (warp >> 2) * 32;     // 2(m) x 4(n) warps, 32x32 each
    const int wn = (warp & 3) * 32;

    float acc[2][4][4];
    #pragma unroll
    for (int i = 0; i < 2; i++)
        #pragma unroll
        for (int j = 0; j < 4; j++)
            #pragma unroll
            for (int r = 0; r < 4; r++) acc[i][j][r] = 0.f;

    // X staging (cp.async bf16): rows tid>>3 (+32), 16B per thread per row
    const int xrow = tid >> 3, xseg = tid & 7;
    const __nv_bfloat16* Xg = X + (size_t)(m0 + xrow) * K + k0 + xseg * 8;

    // W half staging: half = 32 k-rows x 128 cols fp32. 8 threads/row, 4 float4.
    const int hrow = tid >> 3, hseg = tid & 7;
    const float* Wg = W + (size_t)(k0 + hrow) * N + n0 + hseg * 4;

    auto prefetchX = [&](int stage, int i) {
        __nv_bfloat16* Xs = sm + stage * STAGE_ELEMS;
        const __nv_bfloat16* src = Xg + i * 64;
        cp16(Xs + xrow * XS_STRIDE + xseg * 8,        src);
        cp16(Xs + (xrow + 32) * XS_STRIDE + xseg * 8, src + (size_t)32 * K);
    };

    float4 buf[2][4];
    auto ldgW_half = [&](int i, int h, int p) {
        const float* wp = Wg + (size_t)(i * 64 + h * 32) * N;
        #pragma unroll
        for (int j = 0; j < 4; j++)
            buf[p][j] = *reinterpret_cast<const float4*>(wp + j * 32);
    };
    auto stsW_half = [&](int stage, int h, int p) {
        __nv_bfloat16* Ws = sm + stage * STAGE_ELEMS + XS_ELEMS
                          + (h * 32 + hrow) * WS_STRIDE + hseg * 4;
        #pragma unroll
        for (int j = 0; j < 4; j++) {
            float4 v = buf[p][j];
            *reinterpret_cast<uint2*>(Ws + j * 32)
                = make_uint2(pack_bf16(v.x, v.y), pack_bf16(v.z, v.w));
        }
    };

    const int a_row = wm + (lane & 15);
    const int a_col = (lane >> 4) * 8;
    const int b_row = (lane & 7) + ((lane >> 3) & 1) * 8;
    const int b_col = wn + (lane >> 4) * 8;

    auto compute_half = [&](int stage, int h) {
        const __nv_bfloat16* Xs = sm + stage * STAGE_ELEMS;
        const __nv_bfloat16* Ws = Xs + XS_ELEMS;
        uint32_t a0 = (uint32_t)__cvta_generic_to_shared(Xs + a_row * XS_STRIDE + a_col);
        uint32_t a1 = a0 + 16 * XS_STRIDE * 2;
        uint32_t b0a = (uint32_t)__cvta_generic_to_shared(Ws + b_row * WS_STRIDE + b_col);
        uint32_t b1a = b0a + 16 * 2;
        #pragma unroll
        for (int s = 2 * h; s < 2 * h + 2; s++) {
            uint32_t A0[4], A1[4], B0[4], B1[4];
            ldsm4 (A0, a0  + s * 32);
            ldsm4 (A1, a1  + s * 32);
            ldsm4t(B0, b0a + s * 16 * WS_STRIDE * 2);
            ldsm4t(B1, b1a + s * 16 * WS_STRIDE * 2);
            mma16816(acc[0][0], A0, B0[0], B0[1]);
            mma16816(acc[0][1], A0, B0[2], B0[3]);
            mma16816(acc[0][2], A0, B1[0], B1[1]);
            mma16816(acc[0][3], A0, B1[2], B1[3]);
            mma16816(acc[1][0], A1, B0[0], B0[1]);
            mma16816(acc[1][1], A1, B0[2], B0[3]);
            mma16816(acc[1][2], A1, B1[0], B1[1]);
            mma16816(acc[1][3], A1, B1[2], B1[3]);
        }
    };

    // ---- prologue: X stages 0,1,2 in flight; W(0) staged; W(1) in regs ----
    prefetchX(0, 0); cp_commit();
    if (iters > 1) prefetchX(1, 1);
    cp_commit();
    if (iters > 2) prefetchX(2, 2);
    cp_commit();
    ldgW_half(0, 0, 0); ldgW_half(0, 1, 1);
    stsW_half(0, 0, 0); stsW_half(0, 1, 1);
    if (iters > 1) { ldgW_half(1, 0, 0); ldgW_half(1, 1, 1); }
    cp_wait<2>(); __syncthreads();

    // ---- mainloop: 1 sync per iter; W LDG->STS spans a full iteration ----
    for (int i = 0; i < iters; i++) {
        if (i + 3 < iters) prefetchX((i + 3) % NSTAGE, i + 3);
        cp_commit();
        const int si = i % NSTAGE, s1 = (i + 1) % NSTAGE;

        if (i + 1 < iters) stsW_half(s1, 0, 0);     // W(i+1,h0), loaded iter i-1
        if (i + 2 < iters) ldgW_half(i + 2, 0, 0);  // W(i+2,h0)
        compute_half(si, 0);

        if (i + 1 < iters) stsW_half(s1, 1, 1);
        if (i + 2 < iters) ldgW_half(i + 2, 1, 1);
        compute_half(si, 1);

        cp_wait<2>(); __syncthreads();
    }

    // ---- epilogue ----
    #pragma unroll
    for (int mt = 0; mt < 2; mt++) {
        int r = m0 + wm + mt * 16 + g;
        #pragma unroll
        for (int nt = 0; nt < 4; nt++) {
            int c = n0 + wn + nt * 8 + 2 * t;
            float* p0 = &Y[(size_t)r * N + c];
            float* p1 = &Y[(size_t)(r + 8) * N + c];
            if (direct) {
                p0[0] = acc[mt][nt][0]; p0[1] = acc[mt][nt][1];
                p1[0] = acc[mt][nt][2]; p1[1] = acc[mt][nt][3];
            } else {
                atomicAdd(p0,     acc[mt][nt][0]);
                atomicAdd(p0 + 1, acc[mt][nt][1]);
                atomicAdd(p1,     acc[mt][nt][2]);
                atomicAdd(p1 + 1, acc[mt][nt][3]);
            }
        }
    }
}

// ---------------- GCN aggregation (per-sample CTA), bf16 feature out ----------------
__global__ __launch_bounds__(256) void gcn_agg(
    const float* __restrict__ H, const int* __restrict__ ei,
    const float* __restrict__ bias, __nv_bfloat16* __restrict__ Xout,
    float* __restrict__ pooled)
{
    __shared__ int   s_src[450];
    __shared__ float s_norm[450];
    __shared__ int   s_cnt[50], s_start[50], s_cur[50];
    __shared__ float s_dinv[50];
    __shared__ float s_pool[128];

    const int b = blockIdx.x, tid = threadIdx.x;
    const int* eb = ei + (size_t)b * 800;

    if (tid < 50)  s_cnt[tid] = 0;
    if (tid < 128) s_pool[tid] = 0.f;
    __syncthreads();

    for (int e = tid; e < 450; e += 256) {
        int dst = (e < 400) ? eb[400 + e] : (e - 400);
        atomicAdd(&s_cnt[dst], 1);
    }
    __syncthreads();

    if (tid < 50) s_dinv[tid] = rsqrtf((float)s_cnt[tid]);
    if (tid == 0) {
        int s = 0;
        for (int i = 0; i < 50; i++) { s_start[i] = s; s += s_cnt[i]; }
    }
    __syncthreads();
    if (tid < 50) s_cur[tid] = s_start[tid];
    __syncthreads();

    for (int e = tid; e < 450; e += 256) {
        int src, dst;
        if (e < 400) { src = eb[e]; dst = eb[400 + e]; }
        else         { src = dst = e - 400; }
        int pos = atomicAdd(&s_cur[dst], 1);
        s_src[pos]  = src;
        s_norm[pos] = s_dinv[src] * s_dinv[dst];
    }
    __syncthreads();

    const int f  = tid & 127;
    const int n0 = tid >> 7;
    const float* Hb = H + (size_t)b * 50 * 128;
    float pp = 0.f;
    for (int n = n0; n < 50; n += 2) {
        float acc = 0.f;
        int st = s_start[n], en = st + s_cnt[n];
        for (int j = st; j < en; j++)
            acc += s_norm[j] * Hb[s_src[j] * 128 + f];
        float v = lrelu(acc + bias[f]);
        if (Xout) Xout[(size_t)(b * 50 + n) * 128 + f] = __float2bfloat16(v);
        pp += v;
    }
    if (pooled) {
        atomicAdd(&s_pool[f], pp);
        __syncthreads();
        if (tid < 128) pooled[b * 128 + tid] = s_pool[tid] * (1.0f / 50.0f);
    }
}

// ---------------- head: FC1 -> FC2 -> cumsum (warp scan) -> sigmoid ----------------
__global__ __launch_bounds__(256) void head_kernel(
    const float* __restrict__ pooled,
    const float* __restrict__ Wf1, const float* __restrict__ bf1,
    const float* __restrict__ Wf2, const float* __restrict__ bf2,
    float* __restrict__ out)
{
    __shared__ float s_p[128];
    __shared__ float s_z1[64];
    __shared__ float s_z2[2000];

    const int b = blockIdx.x, tid = threadIdx.x;
    if (tid < 128) s_p[tid] = pooled[b * 128 + tid];
    __syncthreads();

    if (tid < 64) {
        float a = bf1[tid];
        #pragma unroll 8
        for (int k = 0; k < 128; k++) a += s_p[k] * Wf1[k * 64 + tid];
        s_z1[tid] = lrelu(a);
    }
    __syncthreads();

    for (int j = tid; j < 2000; j += 256) {
        float a = bf2[j];
        #pragma unroll
        for (int k = 0; k < 64; k++) a += s_z1[k] * Wf2[k * 2000 + j];
        s_z2[j] = a;
    }
    __syncthreads();

    if (tid < 64) {
        int c = tid >> 5, l = tid & 31;
        int k0 = l * 32, k1 = (k0 + 32 < 1000) ? k0 + 32 : 1000;
        float s = 0.f;
        for (int k = k0; k < k1; k++) s += s_z2[2 * k + c];
        float run = s;
        #pragma unroll
        for (int d = 1; d < 32; d <<= 1) {
            float v = __shfl_up_sync(0xffffffff, run, d);
            if (l >= d) run += v;
        }
        float a = run - s;
        float* ob = out + (size_t)b * 2000;
        for (int k = k0; k < k1; k++) {
            a += s_z2[2 * k + c];
            ob[2 * k + c] = 1.f / (1.f + expf(-a));
        }
    }
}

// ---------------- launch ----------------
extern "C" void kernel_launch(void* const* d_in, const int* in_sizes, int n_in,
                              void* d_out, int out_size)
{
    const float* bin = (const float*)d_in[0];
    const int*   ei  = (const int*)  d_in[1];
    const float* W1  = (const float*)d_in[2];
    const float* b1  = (const float*)d_in[3];
    const float* W2  = (const float*)d_in[4];
    const float* b2  = (const float*)d_in[5];
    const float* W3  = (const float*)d_in[6];
    const float* b3  = (const float*)d_in[7];
    const float* Wc1 = (const float*)d_in[8];
    const float* bc1 = (const float*)d_in[9];
    const float* Wc2 = (const float*)d_in[10];
    const float* bc2 = (const float*)d_in[11];
    const float* Wf1 = (const float*)d_in[12];
    const float* bf1 = (const float*)d_in[13];
    const float* Wf2 = (const float*)d_in[14];
    const float* bf2 = (const float*)d_in[15];
    float* out = (float*)d_out;

    float *Y1, *Y2, *Y3, *H, *PL;
    __nv_bfloat16 *Xin, *Xb1, *Xb2, *Xb3, *X2b;
    cudaGetSymbolAddress((void**)&Y1,  g_Y1);
    cudaGetSymbolAddress((void**)&Y2,  g_Y2);
    cudaGetSymbolAddress((void**)&Y3,  g_Y3);
    cudaGetSymbolAddress((void**)&Xin, g_Xin);
    cudaGetSymbolAddress((void**)&Xb1, g_Xb1);
    cudaGetSymbolAddress((void**)&Xb2, g_Xb2);
    cudaGetSymbolAddress((void**)&Xb3, g_Xb3);
    cudaGetSymbolAddress((void**)&X2b, g_X2b);
    cudaGetSymbolAddress((void**)&H,   g_H);
    cudaGetSymbolAddress((void**)&PL,  g_PL);

    cudaFuncSetAttribute(gemm_bf16, cudaFuncAttributeMaxDynamicSharedMemorySize,
                         GEMM_SMEM_BYTES);

    prep_kernel<<<3000, 256>>>((float4*)Y1, (const float4*)b1,
                               (float4*)Y2, (const float4*)b2,
                               (float4*)Y3, (const float4*)b3,
                               (const float4*)bin, (uint2*)Xin);

    // encoder L1: (64,25600)@(25600,3200); 12 K-chunks of 2176 -> 300 CTAs
    gemm_bf16<<<dim3(25, 12, 1), 256, GEMM_SMEM_BYTES>>>(Xin, W1, Y1, 25600, 3200, 2176, 0);
    post_act<<<(51200 + 255) / 256, 256>>>((const float4*)Y1, (uint2*)Xb1, 51200, 1);

    // encoder L2: (64,3200)@(3200,6400); 6 K-chunks of 576 -> 300 CTAs
    gemm_bf16<<<dim3(50, 6, 1), 256, GEMM_SMEM_BYTES>>>(Xb1, W2, Y2, 3200, 6400, 576, 0);
    post_act<<<(102400 + 255) / 256, 256>>>((const float4*)Y2, (uint2*)Xb2, 102400, 1);

    // encoder L3 (no act): (64,6400)@(6400,12800); 3 K-chunks of 2176 -> 300 CTAs
    gemm_bf16<<<dim3(100, 3, 1), 256, GEMM_SMEM_BYTES>>>(Xb2, W3, Y3, 6400, 12800, 2176, 0);
    post_act<<<(204800 + 255) / 256, 256>>>((const float4*)Y3, (uint2*)Xb3, 204800, 0);

    // GCN L1: H = nodes(3200,256)@Wc1(256,128), direct store
    gemm_bf16<<<dim3(1, 1, 50), 256, GEMM_SMEM_BYTES>>>(Xb3, Wc1, H, 256, 128, 256, 1);
    gcn_agg<<<64, 256>>>(H, ei, bc1, X2b, nullptr);

    // GCN L2: H = X2(3200,128)@Wc2(128,128), direct store
    gemm_bf16<<<dim3(1, 1, 50), 256, GEMM_SMEM_BYTES>>>(X2b, Wc2, H, 128, 128, 128, 1);
    gcn_agg<<<64, 256>>>(H, ei, bc2, nullptr, PL);

    head_kernel<<<64, 256>>>(PL, Wf1, bf1, Wf2, bf2, out);
}

// round 11
// speedup vs baseline: 1.0529x; 1.0529x over previous
#include <cuda_runtime.h>
#include <cuda_bf16.h>
#include <cstdint>

#define NEG 0.01f
__device__ __forceinline__ float lrelu(float v) { return v >= 0.f ? v : NEG * v; }

// ---- bf16 GEMM tile: CTA 64(M) x 128(N) x 64(K) per iter, 3-stage smem ring ----
#define XS_STRIDE 72            // bf16 (64 + 8 pad) -> 144B rows, LDSM conflict-free
#define WS_STRIDE 136           // bf16 (128 + 8 pad) -> 272B rows
#define XS_ELEMS (64 * XS_STRIDE)
#define WS_ELEMS (64 * WS_STRIDE)
#define STAGE_ELEMS (XS_ELEMS + WS_ELEMS)          // 13312 bf16
#define NSTAGE 3
#define GEMM_SMEM_BYTES (NSTAGE * STAGE_ELEMS * 2) // 79872 B

// ---------------- scratch (device globals) ----------------
__device__ float g_Y1[64 * 3200];
__device__ float g_Y2[64 * 6400];
__device__ float g_Y3[64 * 12800];
__device__ __nv_bfloat16 g_Xin[64 * 25600];
__device__ __nv_bfloat16 g_Xb1[64 * 3200];
__device__ __nv_bfloat16 g_Xb2[64 * 6400];
__device__ __nv_bfloat16 g_Xb3[64 * 12800];
__device__ __nv_bfloat16 g_X2b[64 * 50 * 128];
__device__ float g_H [64 * 50 * 128];
__device__ float g_PL[64 * 128];

// ---------------- helpers ----------------
__device__ __forceinline__ uint32_t pack_bf16(float lo, float hi) {
    uint32_t r;
    asm("cvt.rn.bf16x2.f32 %0, %1, %2;" : "=r"(r) : "f"(hi), "f"(lo));
    return r;
}
__device__ __forceinline__ void cp16(void* dst_smem, const void* src) {
    uint32_t d = (uint32_t)__cvta_generic_to_shared(dst_smem);
    asm volatile("cp.async.cg.shared.global [%0], [%1], 16;\n" :: "r"(d), "l"(src));
}
__device__ __forceinline__ void cp_commit() { asm volatile("cp.async.commit_group;\n"); }
template<int NN> __device__ __forceinline__ void cp_wait() {
    asm volatile("cp.async.wait_group %0;\n" :: "n"(NN));
}
__device__ __forceinline__ void ldsm4(uint32_t* r, uint32_t addr) {
    asm volatile("ldmatrix.sync.aligned.m8n8.x4.shared.b16 {%0,%1,%2,%3}, [%4];"
                 : "=r"(r[0]), "=r"(r[1]), "=r"(r[2]), "=r"(r[3]) : "r"(addr));
}
__device__ __forceinline__ void ldsm4t(uint32_t* r, uint32_t addr) {
    asm volatile("ldmatrix.sync.aligned.m8n8.x4.trans.shared.b16 {%0,%1,%2,%3}, [%4];"
                 : "=r"(r[0]), "=r"(r[1]), "=r"(r[2]), "=r"(r[3]) : "r"(addr));
}
__device__ __forceinline__ void mma16816(float* c, const uint32_t* a, uint32_t b0, uint32_t b1) {
    asm("mma.sync.aligned.m16n8k16.row.col.f32.bf16.bf16.f32 "
        "{%0,%1,%2,%3}, {%4,%5,%6,%7}, {%8,%9}, {%0,%1,%2,%3};"
        : "+f"(c[0]), "+f"(c[1]), "+f"(c[2]), "+f"(c[3])
        : "r"(a[0]), "r"(a[1]), "r"(a[2]), "r"(a[3]), "r"(b0), "r"(b1));
}

// ---------------- prep: bias-init Y1..Y3, convert input b -> bf16 ----------------
__global__ void prep_kernel(float4* __restrict__ Y1, const float4* __restrict__ B1,
                            float4* __restrict__ Y2, const float4* __restrict__ B2,
                            float4* __restrict__ Y3, const float4* __restrict__ B3,
                            const float4* __restrict__ bin, uint2* __restrict__ Xin) {
    int i = blockIdx.x * 256 + threadIdx.x;
    if (i < 51200)        Y1[i] = B1[i % 800];
    else if (i < 153600)  { int j = i - 51200;  Y2[j] = B2[j % 1600]; }
    else if (i < 358400)  { int j = i - 153600; Y3[j] = B3[j % 3200]; }
    else if (i < 768000)  {
        int j = i - 358400;
        float4 v = bin[j];
        Xin[j] = make_uint2(pack_bf16(v.x, v.y), pack_bf16(v.z, v.w));
    }
}

// ---------------- post pass: fp32 Y -> (leaky) -> bf16 X ----------------
__global__ void post_act(const float4* __restrict__ Y, uint2* __restrict__ Xb,
                         int n4, int leak) {
    int i = blockIdx.x * 256 + threadIdx.x;
    if (i < n4) {
        float4 v = Y[i];
        if (leak) { v.x = lrelu(v.x); v.y = lrelu(v.y); v.z = lrelu(v.z); v.w = lrelu(v.w); }
        Xb[i] = make_uint2(pack_bf16(v.x, v.y), pack_bf16(v.z, v.w));
    }
}

// ---------------- bf16 mma GEMM (R7 structure) ----------------
// X bf16 via cp.async (3-stage ring, distance 2); W fp32 LDG -> bf16 STS with
// 2 half-K register buffers: LDG->STS distance = 1 full iteration.
// grid: (N/128, numKChunks, M/64). direct=1: plain store (grid.y==1).
// K, chunkLen multiples of 64; N multiple of 128.
__global__ __launch_bounds__(256, 2) void gemm_bf16(
    const __nv_bfloat16* __restrict__ X, const float* __restrict__ W,
    float* __restrict__ Y, int K, int N, int chunkLen, int direct)
{
    extern __shared__ __align__(16) char smraw[];
    __nv_bfloat16* sm = reinterpret_cast<__nv_bfloat16*>(smraw);

    const int tid = threadIdx.x;
    const int warp = tid >> 5, lane = tid & 31;
    const int g = lane >> 2, t = lane & 3;

    const int n0 = blockIdx.x * 128;
    const int m0 = blockIdx.z * 64;
    const int k0 = blockIdx.y * chunkLen;
    int kend = k0 + chunkLen; if (kend > K) kend = K;
    const int iters = (kend - k0) >> 6;

    const int wm = (warp >> 2) * 32;     // 2(m) x 4(n) warps, 32x32 each
    const int wn = (warp & 3) * 32;

    float acc[2][4][4];
    #pragma unroll
    for (int i = 0; i < 2; i++)
        #pragma unroll
        for (int j = 0; j < 4; j++)
            #pragma unroll
            for (int r = 0; r < 4; r++) acc[i][j][r] = 0.f;

    // X staging (cp.async bf16): rows tid>>3 (+32), 16B per thread per row
    const int xrow = tid >> 3, xseg = tid & 7;
    const __nv_bfloat16* Xg = X + (size_t)(m0 + xrow) * K + k0 + xseg * 8;

    // W half staging: half = 32 k-rows x 128 cols fp32. 8 threads/row, 4 float4.
    const int hrow = tid >> 3, hseg = tid & 7;
    const float* Wg = W + (size_t)(k0 + hrow) * N + n0 + hseg * 4;

    auto prefetchX = [&](int stage, int i) {
        __nv_bfloat16* Xs = sm + stage * STAGE_ELEMS;
        const __nv_bfloat16* src = Xg + i * 64;
        cp16(Xs + xrow * XS_STRIDE + xseg * 8,        src);
        cp16(Xs + (xrow + 32) * XS_STRIDE + xseg * 8, src + (size_t)32 * K);
    };

    float4 buf[2][4];
    auto ldgW_half = [&](int i, int h, int p) {
        const float* wp = Wg + (size_t)(i * 64 + h * 32) * N;
        #pragma unroll
        for (int j = 0; j < 4; j++)
            buf[p][j] = *reinterpret_cast<const float4*>(wp + j * 32);
    };
    auto stsW_half = [&](int stage, int h, int p) {
        __nv_bfloat16* Ws = sm + stage * STAGE_ELEMS + XS_ELEMS
                          + (h * 32 + hrow) * WS_STRIDE + hseg * 4;
        #pragma unroll
        for (int j = 0; j < 4; j++) {
            float4 v = buf[p][j];
            *reinterpret_cast<uint2*>(Ws + j * 32)
                = make_uint2(pack_bf16(v.x, v.y), pack_bf16(v.z, v.w));
        }
    };

    const int a_row = wm + (lane & 15);
    const int a_col = (lane >> 4) * 8;
    const int b_row = (lane & 7) + ((lane >> 3) & 1) * 8;
    const int b_col = wn + (lane >> 4) * 8;

    auto compute_half = [&](int stage, int h) {
        const __nv_bfloat16* Xs = sm + stage * STAGE_ELEMS;
        const __nv_bfloat16* Ws = Xs + XS_ELEMS;
        uint32_t a0 = (uint32_t)__cvta_generic_to_shared(Xs + a_row * XS_STRIDE + a_col);
        uint32_t a1 = a0 + 16 * XS_STRIDE * 2;
        uint32_t b0a = (uint32_t)__cvta_generic_to_shared(Ws + b_row * WS_STRIDE + b_col);
        uint32_t b1a = b0a + 16 * 2;
        #pragma unroll
        for (int s = 2 * h; s < 2 * h + 2; s++) {
            uint32_t A0[4], A1[4], B0[4], B1[4];
            ldsm4 (A0, a0  + s * 32);
            ldsm4 (A1, a1  + s * 32);
            ldsm4t(B0, b0a + s * 16 * WS_STRIDE * 2);
            ldsm4t(B1, b1a + s * 16 * WS_STRIDE * 2);
            mma16816(acc[0][0], A0, B0[0], B0[1]);
            mma16816(acc[0][1], A0, B0[2], B0[3]);
            mma16816(acc[0][2], A0, B1[0], B1[1]);
            mma16816(acc[0][3], A0, B1[2], B1[3]);
            mma16816(acc[1][0], A1, B0[0], B0[1]);
            mma16816(acc[1][1], A1, B0[2], B0[3]);
            mma16816(acc[1][2], A1, B1[0], B1[1]);
            mma16816(acc[1][3], A1, B1[2], B1[3]);
        }
    };

    // ---- prologue: X stages 0,1 in flight; W(0) staged; W(1) in regs ----
    prefetchX(0, 0); cp_commit();
    if (iters > 1) prefetchX(1, 1);
    cp_commit();
    ldgW_half(0, 0, 0); ldgW_half(0, 1, 1);
    stsW_half(0, 0, 0); stsW_half(0, 1, 1);
    if (iters > 1) { ldgW_half(1, 0, 0); ldgW_half(1, 1, 1); }
    cp_wait<1>(); __syncthreads();

    // ---- mainloop: 1 sync per iter; W LDG->STS spans a full iteration ----
    for (int i = 0; i < iters; i++) {
        if (i + 2 < iters) prefetchX((i + 2) % NSTAGE, i + 2);
        cp_commit();
        const int si = i % NSTAGE, s1 = (i + 1) % NSTAGE;

        if (i + 1 < iters) stsW_half(s1, 0, 0);     // W(i+1,h0), loaded iter i-1
        if (i + 2 < iters) ldgW_half(i + 2, 0, 0);  // W(i+2,h0)
        compute_half(si, 0);

        if (i + 1 < iters) stsW_half(s1, 1, 1);
        if (i + 2 < iters) ldgW_half(i + 2, 1, 1);
        compute_half(si, 1);

        cp_wait<1>(); __syncthreads();
    }

    // ---- epilogue ----
    #pragma unroll
    for (int mt = 0; mt < 2; mt++) {
        int r = m0 + wm + mt * 16 + g;
        #pragma unroll
        for (int nt = 0; nt < 4; nt++) {
            int c = n0 + wn + nt * 8 + 2 * t;
            float* p0 = &Y[(size_t)r * N + c];
            float* p1 = &Y[(size_t)(r + 8) * N + c];
            if (direct) {
                p0[0] = acc[mt][nt][0]; p0[1] = acc[mt][nt][1];
                p1[0] = acc[mt][nt][2]; p1[1] = acc[mt][nt][3];
            } else {
                atomicAdd(p0,     acc[mt][nt][0]);
                atomicAdd(p0 + 1, acc[mt][nt][1]);
                atomicAdd(p1,     acc[mt][nt][2]);
                atomicAdd(p1 + 1, acc[mt][nt][3]);
            }
        }
    }
}

// ---------------- GCN aggregation (per-sample CTA), bf16 feature out ----------------
__global__ __launch_bounds__(256) void gcn_agg(
    const float* __restrict__ H, const int* __restrict__ ei,
    const float* __restrict__ bias, __nv_bfloat16* __restrict__ Xout,
    float* __restrict__ pooled)
{
    __shared__ int   s_src[450];
    __shared__ float s_norm[450];
    __shared__ int   s_cnt[50], s_start[50], s_cur[50];
    __shared__ float s_dinv[50];
    __shared__ float s_pool[128];

    const int b = blockIdx.x, tid = threadIdx.x;
    const int* eb = ei + (size_t)b * 800;

    if (tid < 50)  s_cnt[tid] = 0;
    if (tid < 128) s_pool[tid] = 0.f;
    __syncthreads();

    for (int e = tid; e < 450; e += 256) {
        int dst = (e < 400) ? eb[400 + e] : (e - 400);
        atomicAdd(&s_cnt[dst], 1);
    }
    __syncthreads();

    if (tid < 50) s_dinv[tid] = rsqrtf((float)s_cnt[tid]);
    if (tid == 0) {
        int s = 0;
        for (int i = 0; i < 50; i++) { s_start[i] = s; s += s_cnt[i]; }
    }
    __syncthreads();
    if (tid < 50) s_cur[tid] = s_start[tid];
    __syncthreads();

    for (int e = tid; e < 450; e += 256) {
        int src, dst;
        if (e < 400) { src = eb[e]; dst = eb[400 + e]; }
        else         { src = dst = e - 400; }
        int pos = atomicAdd(&s_cur[dst], 1);
        s_src[pos]  = src;
        s_norm[pos] = s_dinv[src] * s_dinv[dst];
    }
    __syncthreads();

    const int f  = tid & 127;
    const int n0 = tid >> 7;
    const float* Hb = H + (size_t)b * 50 * 128;
    float pp = 0.f;
    for (int n = n0; n < 50; n += 2) {
        float acc = 0.f;
        int st = s_start[n], en = st + s_cnt[n];
        for (int j = st; j < en; j++)
            acc += s_norm[j] * Hb[s_src[j] * 128 + f];
        float v = lrelu(acc + bias[f]);
        if (Xout) Xout[(size_t)(b * 50 + n) * 128 + f] = __float2bfloat16(v);
        pp += v;
    }
    if (pooled) {
        atomicAdd(&s_pool[f], pp);
        __syncthreads();
        if (tid < 128) pooled[b * 128 + tid] = s_pool[tid] * (1.0f / 50.0f);
    }
}

// ---------------- head: FC1 -> FC2 -> cumsum (warp scan) -> sigmoid ----------------
__global__ __launch_bounds__(256) void head_kernel(
    const float* __restrict__ pooled,
    const float* __restrict__ Wf1, const float* __restrict__ bf1,
    const float* __restrict__ Wf2, const float* __restrict__ bf2,
    float* __restrict__ out)
{
    __shared__ float s_p[128];
    __shared__ float s_z1[64];
    __shared__ float s_z2[2000];

    const int b = blockIdx.x, tid = threadIdx.x;
    if (tid < 128) s_p[tid] = pooled[b * 128 + tid];
    __syncthreads();

    if (tid < 64) {
        float a = bf1[tid];
        #pragma unroll 8
        for (int k = 0; k < 128; k++) a += s_p[k] * Wf1[k * 64 + tid];
        s_z1[tid] = lrelu(a);
    }
    __syncthreads();

    for (int j = tid; j < 2000; j += 256) {
        float a = bf2[j];
        #pragma unroll
        for (int k = 0; k < 64; k++) a += s_z1[k] * Wf2[k * 2000 + j];
        s_z2[j] = a;
    }
    __syncthreads();

    if (tid < 64) {
        int c = tid >> 5, l = tid & 31;
        int k0 = l * 32, k1 = (k0 + 32 < 1000) ? k0 + 32 : 1000;
        float s = 0.f;
        for (int k = k0; k < k1; k++) s += s_z2[2 * k + c];
        float run = s;
        #pragma unroll
        for (int d = 1; d < 32; d <<= 1) {
            float v = __shfl_up_sync(0xffffffff, run, d);
            if (l >= d) run += v;
        }
        float a = run - s;
        float* ob = out + (size_t)b * 2000;
        for (int k = k0; k < k1; k++) {
            a += s_z2[2 * k + c];
            ob[2 * k + c] = 1.f / (1.f + expf(-a));
        }
    }
}

// ---------------- launch ----------------
extern "C" void kernel_launch(void* const* d_in, const int* in_sizes, int n_in,
                              void* d_out, int out_size)
{
    const float* bin = (const float*)d_in[0];
    const int*   ei  = (const int*)  d_in[1];
    const float* W1  = (const float*)d_in[2];
    const float* b1  = (const float*)d_in[3];
    const float* W2  = (const float*)d_in[4];
    const float* b2  = (const float*)d_in[5];
    const float* W3  = (const float*)d_in[6];
    const float* b3  = (const float*)d_in[7];
    const float* Wc1 = (const float*)d_in[8];
    const float* bc1 = (const float*)d_in[9];
    const float* Wc2 = (const float*)d_in[10];
    const float* bc2 = (const float*)d_in[11];
    const float* Wf1 = (const float*)d_in[12];
    const float* bf1 = (const float*)d_in[13];
    const float* Wf2 = (const float*)d_in[14];
    const float* bf2 = (const float*)d_in[15];
    float* out = (float*)d_out;

    float *Y1, *Y2, *Y3, *H, *PL;
    __nv_bfloat16 *Xin, *Xb1, *Xb2, *Xb3, *X2b;
    cudaGetSymbolAddress((void**)&Y1,  g_Y1);
    cudaGetSymbolAddress((void**)&Y2,  g_Y2);
    cudaGetSymbolAddress((void**)&Y3,  g_Y3);
    cudaGetSymbolAddress((void**)&Xin, g_Xin);
    cudaGetSymbolAddress((void**)&Xb1, g_Xb1);
    cudaGetSymbolAddress((void**)&Xb2, g_Xb2);
    cudaGetSymbolAddress((void**)&Xb3, g_Xb3);
    cudaGetSymbolAddress((void**)&X2b, g_X2b);
    cudaGetSymbolAddress((void**)&H,   g_H);
    cudaGetSymbolAddress((void**)&PL,  g_PL);

    cudaFuncSetAttribute(gemm_bf16, cudaFuncAttributeMaxDynamicSharedMemorySize,
                         GEMM_SMEM_BYTES);

    prep_kernel<<<3000, 256>>>((float4*)Y1, (const float4*)b1,
                               (float4*)Y2, (const float4*)b2,
                               (float4*)Y3, (const float4*)b3,
                               (const float4*)bin, (uint2*)Xin);

    // encoder L1: (64,25600)@(25600,3200); 11 K-chunks of 2368 -> 275 CTAs (<296, single wave)
    gemm_bf16<<<dim3(25, 11, 1), 256, GEMM_SMEM_BYTES>>>(Xin, W1, Y1, 25600, 3200, 2368, 0);
    post_act<<<(51200 + 255) / 256, 256>>>((const float4*)Y1, (uint2*)Xb1, 51200, 1);

    // encoder L2: (64,3200)@(3200,6400); 5 K-chunks of 640 -> 250 CTAs (single wave)
    gemm_bf16<<<dim3(50, 5, 1), 256, GEMM_SMEM_BYTES>>>(Xb1, W2, Y2, 3200, 6400, 640, 0);
    post_act<<<(102400 + 255) / 256, 256>>>((const float4*)Y2, (uint2*)Xb2, 102400, 1);

    // encoder L3 (no act): (64,6400)@(6400,12800); 2 K-chunks of 3200 -> 200 CTAs (single wave)
    gemm_bf16<<<dim3(100, 2, 1), 256, GEMM_SMEM_BYTES>>>(Xb2, W3, Y3, 6400, 12800, 3200, 0);
    post_act<<<(204800 + 255) / 256, 256>>>((const float4*)Y3, (uint2*)Xb3, 204800, 0);

    // GCN L1: H = nodes(3200,256)@Wc1(256,128), direct store
    gemm_bf16<<<dim3(1, 1, 50), 256, GEMM_SMEM_BYTES>>>(Xb3, Wc1, H, 256, 128, 256, 1);
    gcn_agg<<<64, 256>>>(H, ei, bc1, X2b, nullptr);

    // GCN L2: H = X2(3200,128)@Wc2(128,128), direct store
    gemm_bf16<<<dim3(1, 1, 50), 256, GEMM_SMEM_BYTES>>>(X2b, Wc2, H, 128, 128, 128, 1);
    gcn_agg<<<64, 256>>>(H, ei, bc2, nullptr, PL);

    head_kernel<<<64, 256>>>(PL, Wf1, bf1, Wf2, bf2, out);
}

// round 12
// speedup vs baseline: 1.0931x; 1.0382x over previous
#include <cuda_runtime.h>
#include <cuda_bf16.h>
#include <cstdint>

#define NEG 0.01f
__device__ __forceinline__ float lrelu(float v) { return v >= 0.f ? v : NEG * v; }

// ---- bf16 GEMM tile: CTA 64(M) x 128(N) x 64(K) per iter, 3-stage smem ring ----
#define XS_STRIDE 72            // bf16 (64 + 8 pad) -> 144B rows, LDSM conflict-free
#define WS_STRIDE 136           // bf16 (128 + 8 pad) -> 272B rows
#define XS_ELEMS (64 * XS_STRIDE)
#define WS_ELEMS (64 * WS_STRIDE)
#define STAGE_ELEMS (XS_ELEMS + WS_ELEMS)          // 13312 bf16
#define NSTAGE 3
#define GEMM_SMEM_BYTES (NSTAGE * STAGE_ELEMS * 2) // 79872 B
#define PF_DIST 4               // W L2-prefetch distance in iterations

// ---------------- scratch (device globals) ----------------
__device__ float g_Y1[64 * 3200];
__device__ float g_Y2[64 * 6400];
__device__ float g_Y3[64 * 12800];
__device__ __nv_bfloat16 g_Xin[64 * 25600];
__device__ __nv_bfloat16 g_Xb1[64 * 3200];
__device__ __nv_bfloat16 g_Xb2[64 * 6400];
__device__ __nv_bfloat16 g_Xb3[64 * 12800];
__device__ __nv_bfloat16 g_X2b[64 * 50 * 128];
__device__ float g_H [64 * 50 * 128];
__device__ float g_PL[64 * 128];

// ---------------- helpers ----------------
__device__ __forceinline__ uint32_t pack_bf16(float lo, float hi) {
    uint32_t r;
    asm("cvt.rn.bf16x2.f32 %0, %1, %2;" : "=r"(r) : "f"(hi), "f"(lo));
    return r;
}
__device__ __forceinline__ void cp16(void* dst_smem, const void* src) {
    uint32_t d = (uint32_t)__cvta_generic_to_shared(dst_smem);
    asm volatile("cp.async.cg.shared.global [%0], [%1], 16;\n" :: "r"(d), "l"(src));
}
__device__ __forceinline__ void cp_commit() { asm volatile("cp.async.commit_group;\n"); }
template<int NN> __device__ __forceinline__ void cp_wait() {
    asm volatile("cp.async.wait_group %0;\n" :: "n"(NN));
}
__device__ __forceinline__ void pref_l2(const void* p) {
    asm volatile("prefetch.global.L2 [%0];" :: "l"(p));
}
__device__ __forceinline__ void ldsm4(uint32_t* r, uint32_t addr) {
    asm volatile("ldmatrix.sync.aligned.m8n8.x4.shared.b16 {%0,%1,%2,%3}, [%4];"
                 : "=r"(r[0]), "=r"(r[1]), "=r"(r[2]), "=r"(r[3]) : "r"(addr));
}
__device__ __forceinline__ void ldsm4t(uint32_t* r, uint32_t addr) {
    asm volatile("ldmatrix.sync.aligned.m8n8.x4.trans.shared.b16 {%0,%1,%2,%3}, [%4];"
                 : "=r"(r[0]), "=r"(r[1]), "=r"(r[2]), "=r"(r[3]) : "r"(addr));
}
__device__ __forceinline__ void mma16816(float* c, const uint32_t* a, uint32_t b0, uint32_t b1) {
    asm("mma.sync.aligned.m16n8k16.row.col.f32.bf16.bf16.f32 "
        "{%0,%1,%2,%3}, {%4,%5,%6,%7}, {%8,%9}, {%0,%1,%2,%3};"
        : "+f"(c[0]), "+f"(c[1]), "+f"(c[2]), "+f"(c[3])
        : "r"(a[0]), "r"(a[1]), "r"(a[2]), "r"(a[3]), "r"(b0), "r"(b1));
}

// ---------------- prep: bias-init Y1..Y3, convert input b -> bf16 ----------------
__global__ void prep_kernel(float4* __restrict__ Y1, const float4* __restrict__ B1,
                            float4* __restrict__ Y2, const float4* __restrict__ B2,
                            float4* __restrict__ Y3, const float4* __restrict__ B3,
                            const float4* __restrict__ bin, uint2* __restrict__ Xin) {
    int i = blockIdx.x * 256 + threadIdx.x;
    if (i < 51200)        Y1[i] = B1[i % 800];
    else if (i < 153600)  { int j = i - 51200;  Y2[j] = B2[j % 1600]; }
    else if (i < 358400)  { int j = i - 153600; Y3[j] = B3[j % 3200]; }
    else if (i < 768000)  {
        int j = i - 358400;
        float4 v = bin[j];
        Xin[j] = make_uint2(pack_bf16(v.x, v.y), pack_bf16(v.z, v.w));
    }
}

// ---------------- post pass: fp32 Y -> (leaky) -> bf16 X ----------------
__global__ void post_act(const float4* __restrict__ Y, uint2* __restrict__ Xb,
                         int n4, int leak) {
    int i = blockIdx.x * 256 + threadIdx.x;
    if (i < n4) {
        float4 v = Y[i];
        if (leak) { v.x = lrelu(v.x); v.y = lrelu(v.y); v.z = lrelu(v.z); v.w = lrelu(v.w); }
        Xb[i] = make_uint2(pack_bf16(v.x, v.y), pack_bf16(v.z, v.w));
    }
}

// ---------------- bf16 mma GEMM (R7 structure + W L2 prefetch) ----------------
// X bf16 via cp.async (3-stage ring, distance 2); W fp32 LDG -> bf16 STS with
// 2 half-K register buffers (LDG->STS distance = 1 iter); W lines prefetched
// to L2 PF_DIST iters ahead so demand LDGs hit L2 (~250cyc) not DRAM (~1000).
// grid: (N/128, numKChunks, M/64). direct=1: plain store (grid.y==1).
// K, chunkLen multiples of 64; N multiple of 128.
__global__ __launch_bounds__(256, 2) void gemm_bf16(
    const __nv_bfloat16* __restrict__ X, const float* __restrict__ W,
    float* __restrict__ Y, int K, int N, int chunkLen, int direct)
{
    extern __shared__ __align__(16) char smraw[];
    __nv_bfloat16* sm = reinterpret_cast<__nv_bfloat16*>(smraw);

    const int tid = threadIdx.x;
    const int warp = tid >> 5, lane = tid & 31;
    const int g = lane >> 2, t = lane & 3;

    const int n0 = blockIdx.x * 128;
    const int m0 = blockIdx.z * 64;
    const int k0 = blockIdx.y * chunkLen;
    int kend = k0 + chunkLen; if (kend > K) kend = K;
    const int iters = (kend - k0) >> 6;

    const int wm = (warp >> 2) * 32;     // 2(m) x 4(n) warps, 32x32 each
    const int wn = (warp & 3) * 32;

    float acc[2][4][4];
    #pragma unroll
    for (int i = 0; i < 2; i++)
        #pragma unroll
        for (int j = 0; j < 4; j++)
            #pragma unroll
            for (int r = 0; r < 4; r++) acc[i][j][r] = 0.f;

    // X staging (cp.async bf16): rows tid>>3 (+32), 16B per thread per row
    const int xrow = tid >> 3, xseg = tid & 7;
    const __nv_bfloat16* Xg = X + (size_t)(m0 + xrow) * K + k0 + xseg * 8;

    // W half staging: half = 32 k-rows x 128 cols fp32. 8 threads/row, 4 float4.
    const int hrow = tid >> 3, hseg = tid & 7;
    const float* Wg = W + (size_t)(k0 + hrow) * N + n0 + hseg * 4;

    auto prefetchX = [&](int stage, int i) {
        __nv_bfloat16* Xs = sm + stage * STAGE_ELEMS;
        const __nv_bfloat16* src = Xg + i * 64;
        cp16(Xs + xrow * XS_STRIDE + xseg * 8,        src);
        cp16(Xs + (xrow + 32) * XS_STRIDE + xseg * 8, src + (size_t)32 * K);
    };

    // L2 prefetch of W for iter i: each 8-thread row group covers its 512B row
    // (4 x 128B lines, 2x duplicated across hseg) in both 32-row halves.
    const int pfj = (hseg & 3) * 32;
    auto prefWL2 = [&](int i) {
        const float* wp = Wg + (size_t)i * 64 * N;
        pref_l2(wp + pfj);
        pref_l2(wp + (size_t)32 * N + pfj);
    };

    float4 buf[2][4];
    auto ldgW_half = [&](int i, int h, int p) {
        const float* wp = Wg + (size_t)(i * 64 + h * 32) * N;
        #pragma unroll
        for (int j = 0; j < 4; j++)
            buf[p][j] = *reinterpret_cast<const float4*>(wp + j * 32);
    };
    auto stsW_half = [&](int stage, int h, int p) {
        __nv_bfloat16* Ws = sm + stage * STAGE_ELEMS + XS_ELEMS
                          + (h * 32 + hrow) * WS_STRIDE + hseg * 4;
        #pragma unroll
        for (int j = 0; j < 4; j++) {
            float4 v = buf[p][j];
            *reinterpret_cast<uint2*>(Ws + j * 32)
                = make_uint2(pack_bf16(v.x, v.y), pack_bf16(v.z, v.w));
        }
    };

    const int a_row = wm + (lane & 15);
    const int a_col = (lane >> 4) * 8;
    const int b_row = (lane & 7) + ((lane >> 3) & 1) * 8;
    const int b_col = wn + (lane >> 4) * 8;

    auto compute_half = [&](int stage, int h) {
        const __nv_bfloat16* Xs = sm + stage * STAGE_ELEMS;
        const __nv_bfloat16* Ws = Xs + XS_ELEMS;
        uint32_t a0 = (uint32_t)__cvta_generic_to_shared(Xs + a_row * XS_STRIDE + a_col);
        uint32_t a1 = a0 + 16 * XS_STRIDE * 2;
        uint32_t b0a = (uint32_t)__cvta_generic_to_shared(Ws + b_row * WS_STRIDE + b_col);
        uint32_t b1a = b0a + 16 * 2;
        #pragma unroll
        for (int s = 2 * h; s < 2 * h + 2; s++) {
            uint32_t A0[4], A1[4], B0[4], B1[4];
            ldsm4 (A0, a0  + s * 32);
            ldsm4 (A1, a1  + s * 32);
            ldsm4t(B0, b0a + s * 16 * WS_STRIDE * 2);
            ldsm4t(B1, b1a + s * 16 * WS_STRIDE * 2);
            mma16816(acc[0][0], A0, B0[0], B0[1]);
            mma16816(acc[0][1], A0, B0[2], B0[3]);
            mma16816(acc[0][2], A0, B1[0], B1[1]);
            mma16816(acc[0][3], A0, B1[2], B1[3]);
            mma16816(acc[1][0], A1, B0[0], B0[1]);
            mma16816(acc[1][1], A1, B0[2], B0[3]);
            mma16816(acc[1][2], A1, B1[0], B1[1]);
            mma16816(acc[1][3], A1, B1[2], B1[3]);
        }
    };

    // ---- prologue: X stages 0,1 in flight; W(0) staged; W(1) in regs ----
    prefetchX(0, 0); cp_commit();
    if (iters > 1) prefetchX(1, 1);
    cp_commit();
    if (iters > 2) prefWL2(2);
    if (iters > 3) prefWL2(3);
    ldgW_half(0, 0, 0); ldgW_half(0, 1, 1);
    stsW_half(0, 0, 0); stsW_half(0, 1, 1);
    if (iters > 1) { ldgW_half(1, 0, 0); ldgW_half(1, 1, 1); }
    cp_wait<1>(); __syncthreads();

    // ---- mainloop: 1 sync per iter; W LDG->STS spans a full iteration ----
    for (int i = 0; i < iters; i++) {
        if (i + 2 < iters) prefetchX((i + 2) % NSTAGE, i + 2);
        cp_commit();
        if (i + PF_DIST < iters) prefWL2(i + PF_DIST);
        const int si = i % NSTAGE, s1 = (i + 1) % NSTAGE;

        if (i + 1 < iters) stsW_half(s1, 0, 0);     // W(i+1,h0), loaded iter i-1
        if (i + 2 < iters) ldgW_half(i + 2, 0, 0);  // W(i+2,h0)
        compute_half(si, 0);

        if (i + 1 < iters) stsW_half(s1, 1, 1);
        if (i + 2 < iters) ldgW_half(i + 2, 1, 1);
        compute_half(si, 1);

        cp_wait<1>(); __syncthreads();
    }

    // ---- epilogue ----
    #pragma unroll
    for (int mt = 0; mt < 2; mt++) {
        int r = m0 + wm + mt * 16 + g;
        #pragma unroll
        for (int nt = 0; nt < 4; nt++) {
            int c = n0 + wn + nt * 8 + 2 * t;
            float* p0 = &Y[(size_t)r * N + c];
            float* p1 = &Y[(size_t)(r + 8) * N + c];
            if (direct) {
                p0[0] = acc[mt][nt][0]; p0[1] = acc[mt][nt][1];
                p1[0] = acc[mt][nt][2]; p1[1] = acc[mt][nt][3];
            } else {
                atomicAdd(p0,     acc[mt][nt][0]);
                atomicAdd(p0 + 1, acc[mt][nt][1]);
                atomicAdd(p1,     acc[mt][nt][2]);
                atomicAdd(p1 + 1, acc[mt][nt][3]);
            }
        }
    }
}

// ---------------- GCN aggregation (per-sample CTA), bf16 feature out ----------------
__global__ __launch_bounds__(256) void gcn_agg(
    const float* __restrict__ H, const int* __restrict__ ei,
    const float* __restrict__ bias, __nv_bfloat16* __restrict__ Xout,
    float* __restrict__ pooled)
{
    __shared__ int   s_src[450];
    __shared__ float s_norm[450];
    __shared__ int   s_cnt[50], s_start[50], s_cur[50];
    __shared__ float s_dinv[50];
    __shared__ float s_pool[128];

    const int b = blockIdx.x, tid = threadIdx.x;
    const int* eb = ei + (size_t)b * 800;

    if (tid < 50)  s_cnt[tid] = 0;
    if (tid < 128) s_pool[tid] = 0.f;
    __syncthreads();

    for (int e = tid; e < 450; e += 256) {
        int dst = (e < 400) ? eb[400 + e] : (e - 400);
        atomicAdd(&s_cnt[dst], 1);
    }
    __syncthreads();

    if (tid < 50) s_dinv[tid] = rsqrtf((float)s_cnt[tid]);
    if (tid == 0) {
        int s = 0;
        for (int i = 0; i < 50; i++) { s_start[i] = s; s += s_cnt[i]; }
    }
    __syncthreads();
    if (tid < 50) s_cur[tid] = s_start[tid];
    __syncthreads();

    for (int e = tid; e < 450; e += 256) {
        int src, dst;
        if (e < 400) { src = eb[e]; dst = eb[400 + e]; }
        else         { src = dst = e - 400; }
        int pos = atomicAdd(&s_cur[dst], 1);
        s_src[pos]  = src;
        s_norm[pos] = s_dinv[src] * s_dinv[dst];
    }
    __syncthreads();

    const int f  = tid & 127;
    const int n0 = tid >> 7;
    const float* Hb = H + (size_t)b * 50 * 128;
    float pp = 0.f;
    for (int n = n0; n < 50; n += 2) {
        float acc = 0.f;
        int st = s_start[n], en = st + s_cnt[n];
        for (int j = st; j < en; j++)
            acc += s_norm[j] * Hb[s_src[j] * 128 + f];
        float v = lrelu(acc + bias[f]);
        if (Xout) Xout[(size_t)(b * 50 + n) * 128 + f] = __float2bfloat16(v);
        pp += v;
    }
    if (pooled) {
        atomicAdd(&s_pool[f], pp);
        __syncthreads();
        if (tid < 128) pooled[b * 128 + tid] = s_pool[tid] * (1.0f / 50.0f);
    }
}

// ---------------- head: FC1 -> FC2 -> cumsum (warp scan) -> sigmoid ----------------
__global__ __launch_bounds__(256) void head_kernel(
    const float* __restrict__ pooled,
    const float* __restrict__ Wf1, const float* __restrict__ bf1,
    const float* __restrict__ Wf2, const float* __restrict__ bf2,
    float* __restrict__ out)
{
    __shared__ float s_p[128];
    __shared__ float s_z1[64];
    __shared__ float s_z2[2000];

    const int b = blockIdx.x, tid = threadIdx.x;
    if (tid < 128) s_p[tid] = pooled[b * 128 + tid];
    __syncthreads();

    if (tid < 64) {
        float a = bf1[tid];
        #pragma unroll 8
        for (int k = 0; k < 128; k++) a += s_p[k] * Wf1[k * 64 + tid];
        s_z1[tid] = lrelu(a);
    }
    __syncthreads();

    for (int j = tid; j < 2000; j += 256) {
        float a = bf2[j];
        #pragma unroll
        for (int k = 0; k < 64; k++) a += s_z1[k] * Wf2[k * 2000 + j];
        s_z2[j] = a;
    }
    __syncthreads();

    if (tid < 64) {
        int c = tid >> 5, l = tid & 31;
        int k0 = l * 32, k1 = (k0 + 32 < 1000) ? k0 + 32 : 1000;
        float s = 0.f;
        for (int k = k0; k < k1; k++) s += s_z2[2 * k + c];
        float run = s;
        #pragma unroll
        for (int d = 1; d < 32; d <<= 1) {
            float v = __shfl_up_sync(0xffffffff, run, d);
            if (l >= d) run += v;
        }
        float a = run - s;
        float* ob = out + (size_t)b * 2000;
        for (int k = k0; k < k1; k++) {
            a += s_z2[2 * k + c];
            ob[2 * k + c] = 1.f / (1.f + expf(-a));
        }
    }
}

// ---------------- launch ----------------
extern "C" void kernel_launch(void* const* d_in, const int* in_sizes, int n_in,
                              void* d_out, int out_size)
{
    const float* bin = (const float*)d_in[0];
    const int*   ei  = (const int*)  d_in[1];
    const float* W1  = (const float*)d_in[2];
    const float* b1  = (const float*)d_in[3];
    const float* W2  = (const float*)d_in[4];
    const float* b2  = (const float*)d_in[5];
    const float* W3  = (const float*)d_in[6];
    const float* b3  = (const float*)d_in[7];
    const float* Wc1 = (const float*)d_in[8];
    const float* bc1 = (const float*)d_in[9];
    const float* Wc2 = (const float*)d_in[10];
    const float* bc2 = (const float*)d_in[11];
    const float* Wf1 = (const float*)d_in[12];
    const float* bf1 = (const float*)d_in[13];
    const float* Wf2 = (const float*)d_in[14];
    const float* bf2 = (const float*)d_in[15];
    float* out = (float*)d_out;

    float *Y1, *Y2, *Y3, *H, *PL;
    __nv_bfloat16 *Xin, *Xb1, *Xb2, *Xb3, *X2b;
    cudaGetSymbolAddress((void**)&Y1,  g_Y1);
    cudaGetSymbolAddress((void**)&Y2,  g_Y2);
    cudaGetSymbolAddress((void**)&Y3,  g_Y3);
    cudaGetSymbolAddress((void**)&Xin, g_Xin);
    cudaGetSymbolAddress((void**)&Xb1, g_Xb1);
    cudaGetSymbolAddress((void**)&Xb2, g_Xb2);
    cudaGetSymbolAddress((void**)&Xb3, g_Xb3);
    cudaGetSymbolAddress((void**)&X2b, g_X2b);
    cudaGetSymbolAddress((void**)&H,   g_H);
    cudaGetSymbolAddress((void**)&PL,  g_PL);

    cudaFuncSetAttribute(gemm_bf16, cudaFuncAttributeMaxDynamicSharedMemorySize,
                         GEMM_SMEM_BYTES);

    prep_kernel<<<3000, 256>>>((float4*)Y1, (const float4*)b1,
                               (float4*)Y2, (const float4*)b2,
                               (float4*)Y3, (const float4*)b3,
                               (const float4*)bin, (uint2*)Xin);

    // encoder L1: (64,25600)@(25600,3200); 12 K-chunks of 2176 -> 300 CTAs
    gemm_bf16<<<dim3(25, 12, 1), 256, GEMM_SMEM_BYTES>>>(Xin, W1, Y1, 25600, 3200, 2176, 0);
    post_act<<<(51200 + 255) / 256, 256>>>((const float4*)Y1, (uint2*)Xb1, 51200, 1);

    // encoder L2: (64,3200)@(3200,6400); 6 K-chunks of 576 -> 300 CTAs
    gemm_bf16<<<dim3(50, 6, 1), 256, GEMM_SMEM_BYTES>>>(Xb1, W2, Y2, 3200, 6400, 576, 0);
    post_act<<<(102400 + 255) / 256, 256>>>((const float4*)Y2, (uint2*)Xb2, 102400, 1);

    // encoder L3 (no act): (64,6400)@(6400,12800); 3 K-chunks of 2176 -> 300 CTAs
    gemm_bf16<<<dim3(100, 3, 1), 256, GEMM_SMEM_BYTES>>>(Xb2, W3, Y3, 6400, 12800, 2176, 0);
    post_act<<<(204800 + 255) / 256, 256>>>((const float4*)Y3, (uint2*)Xb3, 204800, 0);

    // GCN L1: H = nodes(3200,256)@Wc1(256,128), direct store
    gemm_bf16<<<dim3(1, 1, 50), 256, GEMM_SMEM_BYTES>>>(Xb3, Wc1, H, 256, 128, 256, 1);
    gcn_agg<<<64, 256>>>(H, ei, bc1, X2b, nullptr);

    // GCN L2: H = X2(3200,128)@Wc2(128,128), direct store
    gemm_bf16<<<dim3(1, 1, 50), 256, GEMM_SMEM_BYTES>>>(X2b, Wc2, H, 128, 128, 128, 1);
    gcn_agg<<<64, 256>>>(H, ei, bc2, nullptr, PL);

    head_kernel<<<64, 256>>>(PL, Wf1, bf1, Wf2, bf2, out);
}

// round 13
// speedup vs baseline: 1.2589x; 1.1517x over previous
#include <cuda_runtime.h>
#include <cuda_bf16.h>
#include <cstdint>

#define NEG 0.01f
__device__ __forceinline__ float lrelu(float v) { return v >= 0.f ? v : NEG * v; }

// ---- bf16 GEMM tile: CTA 64(M) x 128(N) x 64(K) per iter, 3-stage smem ring ----
#define XS_STRIDE 72            // bf16 (64 + 8 pad) -> 144B rows, LDSM conflict-free
#define WS_STRIDE 136           // bf16 (128 + 8 pad) -> 272B rows
#define XS_ELEMS (64 * XS_STRIDE)
#define WS_ELEMS (64 * WS_STRIDE)
#define STAGE_ELEMS (XS_ELEMS + WS_ELEMS)          // 13312 bf16
#define NSTAGE 3
#define GEMM_SMEM_BYTES (NSTAGE * STAGE_ELEMS * 2) // 79872 B

// ---------------- scratch (device globals) ----------------
__device__ float g_P[2457600];                 // split-K partials: 12*64*3200 = 6*64*6400 = 3*64*12800
__device__ __nv_bfloat16 g_Xin[64 * 25600];
__device__ __nv_bfloat16 g_Xb1[64 * 3200];
__device__ __nv_bfloat16 g_Xb2[64 * 6400];
__device__ __nv_bfloat16 g_Xb3[64 * 12800];
__device__ __nv_bfloat16 g_X2b[64 * 50 * 128];
__device__ float g_H [64 * 50 * 128];
__device__ float g_PL[64 * 128];

// ---------------- helpers ----------------
__device__ __forceinline__ uint32_t pack_bf16(float lo, float hi) {
    uint32_t r;
    asm("cvt.rn.bf16x2.f32 %0, %1, %2;" : "=r"(r) : "f"(hi), "f"(lo));
    return r;
}
__device__ __forceinline__ void cp16(void* dst_smem, const void* src) {
    uint32_t d = (uint32_t)__cvta_generic_to_shared(dst_smem);
    asm volatile("cp.async.cg.shared.global [%0], [%1], 16;\n" :: "r"(d), "l"(src));
}
__device__ __forceinline__ void cp_commit() { asm volatile("cp.async.commit_group;\n"); }
template<int NN> __device__ __forceinline__ void cp_wait() {
    asm volatile("cp.async.wait_group %0;\n" :: "n"(NN));
}
__device__ __forceinline__ void ldsm4(uint32_t* r, uint32_t addr) {
    asm volatile("ldmatrix.sync.aligned.m8n8.x4.shared.b16 {%0,%1,%2,%3}, [%4];"
                 : "=r"(r[0]), "=r"(r[1]), "=r"(r[2]), "=r"(r[3]) : "r"(addr));
}
__device__ __forceinline__ void ldsm4t(uint32_t* r, uint32_t addr) {
    asm volatile("ldmatrix.sync.aligned.m8n8.x4.trans.shared.b16 {%0,%1,%2,%3}, [%4];"
                 : "=r"(r[0]), "=r"(r[1]), "=r"(r[2]), "=r"(r[3]) : "r"(addr));
}
__device__ __forceinline__ void mma16816(float* c, const uint32_t* a, uint32_t b0, uint32_t b1) {
    asm("mma.sync.aligned.m16n8k16.row.col.f32.bf16.bf16.f32 "
        "{%0,%1,%2,%3}, {%4,%5,%6,%7}, {%8,%9}, {%0,%1,%2,%3};"
        : "+f"(c[0]), "+f"(c[1]), "+f"(c[2]), "+f"(c[3])
        : "r"(a[0]), "r"(a[1]), "r"(a[2]), "r"(a[3]), "r"(b0), "r"(b1));
}

// ---------------- prep: convert input b -> bf16 ----------------
__global__ void prep_kernel(const float4* __restrict__ bin, uint2* __restrict__ Xin) {
    int i = blockIdx.x * 256 + threadIdx.x;
    if (i < 409600) {
        float4 v = bin[i];
        Xin[i] = make_uint2(pack_bf16(v.x, v.y), pack_bf16(v.z, v.w));
    }
}

// ---------------- reduce: sum split-K partials + bias (+leaky) -> bf16 ----------------
// P layout: [chunk][64][N]; total4 = 64*N/4; n4row = N/4
__global__ void reduce_act(const float4* __restrict__ P, const float4* __restrict__ bias,
                           uint2* __restrict__ Xb, int n4row, int total4, int nchunks, int leak) {
    int i = blockIdx.x * 256 + threadIdx.x;
    if (i < total4) {
        float4 s = P[i];
        for (int c = 1; c < nchunks; c++) {
            float4 p = P[i + (size_t)c * total4];
            s.x += p.x; s.y += p.y; s.z += p.z; s.w += p.w;
        }
        float4 b = bias[i % n4row];
        s.x += b.x; s.y += b.y; s.z += b.z; s.w += b.w;
        if (leak) { s.x = lrelu(s.x); s.y = lrelu(s.y); s.z = lrelu(s.z); s.w = lrelu(s.w); }
        Xb[i] = make_uint2(pack_bf16(s.x, s.y), pack_bf16(s.z, s.w));
    }
}

// ---------------- bf16 mma GEMM (R7 structure; partial-sum epilogue) ----------------
// X bf16 via cp.async (3-stage ring, distance 2); W fp32 LDG(.cs) -> bf16 STS with
// 2 half-K register buffers: LDG->STS distance = 1 full iteration.
// grid: (N/128, numKChunks, M/64). direct=1: plain store to Y (grid.y==1).
// direct=0: store partials to Y at [blockIdx.y][64][N] (grid.z==1).
// K, chunkLen multiples of 64; N multiple of 128.
__global__ __launch_bounds__(256, 2) void gemm_bf16(
    const __nv_bfloat16* __restrict__ X, const float* __restrict__ W,
    float* __restrict__ Y, int K, int N, int chunkLen, int direct)
{
    extern __shared__ __align__(16) char smraw[];
    __nv_bfloat16* sm = reinterpret_cast<__nv_bfloat16*>(smraw);

    const int tid = threadIdx.x;
    const int warp = tid >> 5, lane = tid & 31;
    const int g = lane >> 2, t = lane & 3;

    const int n0 = blockIdx.x * 128;
    const int m0 = blockIdx.z * 64;
    const int k0 = blockIdx.y * chunkLen;
    int kend = k0 + chunkLen; if (kend > K) kend = K;
    const int iters = (kend - k0) >> 6;

    const int wm = (warp >> 2) * 32;     // 2(m) x 4(n) warps, 32x32 each
    const int wn = (warp & 3) * 32;

    float acc[2][4][4];
    #pragma unroll
    for (int i = 0; i < 2; i++)
        #pragma unroll
        for (int j = 0; j < 4; j++)
            #pragma unroll
            for (int r = 0; r < 4; r++) acc[i][j][r] = 0.f;

    // X staging (cp.async bf16): rows tid>>3 (+32), 16B per thread per row
    const int xrow = tid >> 3, xseg = tid & 7;
    const __nv_bfloat16* Xg = X + (size_t)(m0 + xrow) * K + k0 + xseg * 8;

    // W half staging: half = 32 k-rows x 128 cols fp32. 8 threads/row, 4 float4.
    const int hrow = tid >> 3, hseg = tid & 7;
    const float* Wg = W + (size_t)(k0 + hrow) * N + n0 + hseg * 4;

    auto prefetchX = [&](int stage, int i) {
        __nv_bfloat16* Xs = sm + stage * STAGE_ELEMS;
        const __nv_bfloat16* src = Xg + i * 64;
        cp16(Xs + xrow * XS_STRIDE + xseg * 8,        src);
        cp16(Xs + (xrow + 32) * XS_STRIDE + xseg * 8, src + (size_t)32 * K);
    };

    float4 buf[2][4];
    auto ldgW_half = [&](int i, int h, int p) {
        const float* wp = Wg + (size_t)(i * 64 + h * 32) * N;
        #pragma unroll
        for (int j = 0; j < 4; j++)
            buf[p][j] = __ldcs(reinterpret_cast<const float4*>(wp + j * 32));
    };
    auto stsW_half = [&](int stage, int h, int p) {
        __nv_bfloat16* Ws = sm + stage * STAGE_ELEMS + XS_ELEMS
                          + (h * 32 + hrow) * WS_STRIDE + hseg * 4;
        #pragma unroll
        for (int j = 0; j < 4; j++) {
            float4 v = buf[p][j];
            *reinterpret_cast<uint2*>(Ws + j * 32)
                = make_uint2(pack_bf16(v.x, v.y), pack_bf16(v.z, v.w));
        }
    };

    const int a_row = wm + (lane & 15);
    const int a_col = (lane >> 4) * 8;
    const int b_row = (lane & 7) + ((lane >> 3) & 1) * 8;
    const int b_col = wn + (lane >> 4) * 8;

    auto compute_half = [&](int stage, int h) {
        const __nv_bfloat16* Xs = sm + stage * STAGE_ELEMS;
        const __nv_bfloat16* Ws = Xs + XS_ELEMS;
        uint32_t a0 = (uint32_t)__cvta_generic_to_shared(Xs + a_row * XS_STRIDE + a_col);
        uint32_t a1 = a0 + 16 * XS_STRIDE * 2;
        uint32_t b0a = (uint32_t)__cvta_generic_to_shared(Ws + b_row * WS_STRIDE + b_col);
        uint32_t b1a = b0a + 16 * 2;
        #pragma unroll
        for (int s = 2 * h; s < 2 * h + 2; s++) {
            uint32_t A0[4], A1[4], B0[4], B1[4];
            ldsm4 (A0, a0  + s * 32);
            ldsm4 (A1, a1  + s * 32);
            ldsm4t(B0, b0a + s * 16 * WS_STRIDE * 2);
            ldsm4t(B1, b1a + s * 16 * WS_STRIDE * 2);
            mma16816(acc[0][0], A0, B0[0], B0[1]);
            mma16816(acc[0][1], A0, B0[2], B0[3]);
            mma16816(acc[0][2], A0, B1[0], B1[1]);
            mma16816(acc[0][3], A0, B1[2], B1[3]);
            mma16816(acc[1][0], A1, B0[0], B0[1]);
            mma16816(acc[1][1], A1, B0[2], B0[3]);
            mma16816(acc[1][2], A1, B1[0], B1[1]);
            mma16816(acc[1][3], A1, B1[2], B1[3]);
        }
    };

    // ---- prologue: X stages 0,1 in flight; W(0) staged; W(1) in regs ----
    prefetchX(0, 0); cp_commit();
    if (iters > 1) prefetchX(1, 1);
    cp_commit();
    ldgW_half(0, 0, 0); ldgW_half(0, 1, 1);
    stsW_half(0, 0, 0); stsW_half(0, 1, 1);
    if (iters > 1) { ldgW_half(1, 0, 0); ldgW_half(1, 1, 1); }
    cp_wait<1>(); __syncthreads();

    // ---- mainloop: 1 sync per iter; W LDG->STS spans a full iteration ----
    for (int i = 0; i < iters; i++) {
        if (i + 2 < iters) prefetchX((i + 2) % NSTAGE, i + 2);
        cp_commit();
        const int si = i % NSTAGE, s1 = (i + 1) % NSTAGE;

        if (i + 1 < iters) stsW_half(s1, 0, 0);     // W(i+1,h0), loaded iter i-1
        if (i + 2 < iters) ldgW_half(i + 2, 0, 0);  // W(i+2,h0)
        compute_half(si, 0);

        if (i + 1 < iters) stsW_half(s1, 1, 1);
        if (i + 2 < iters) ldgW_half(i + 2, 1, 1);
        compute_half(si, 1);

        cp_wait<1>(); __syncthreads();
    }

    // ---- epilogue ----
    if (direct) {
        #pragma unroll
        for (int mt = 0; mt < 2; mt++) {
            int r = m0 + wm + mt * 16 + g;
            #pragma unroll
            for (int nt = 0; nt < 4; nt++) {
                int c = n0 + wn + nt * 8 + 2 * t;
                Y[(size_t)r * N + c]           = acc[mt][nt][0];
                Y[(size_t)r * N + c + 1]       = acc[mt][nt][1];
                Y[(size_t)(r + 8) * N + c]     = acc[mt][nt][2];
                Y[(size_t)(r + 8) * N + c + 1] = acc[mt][nt][3];
            }
        }
    } else {
        // partial slab: [blockIdx.y][64][N]  (m0 == 0 for encoder layers)
        float* P = Y + (size_t)blockIdx.y * 64 * N;
        #pragma unroll
        for (int mt = 0; mt < 2; mt++) {
            int r = wm + mt * 16 + g;
            #pragma unroll
            for (int nt = 0; nt < 4; nt++) {
                int c = n0 + wn + nt * 8 + 2 * t;
                *reinterpret_cast<float2*>(&P[(size_t)r * N + c])
                    = make_float2(acc[mt][nt][0], acc[mt][nt][1]);
                *reinterpret_cast<float2*>(&P[(size_t)(r + 8) * N + c])
                    = make_float2(acc[mt][nt][2], acc[mt][nt][3]);
            }
        }
    }
}

// ---------------- GCN aggregation (per-sample CTA), bf16 feature out ----------------
__global__ __launch_bounds__(256) void gcn_agg(
    const float* __restrict__ H, const int* __restrict__ ei,
    const float* __restrict__ bias, __nv_bfloat16* __restrict__ Xout,
    float* __restrict__ pooled)
{
    __shared__ int   s_src[450];
    __shared__ float s_norm[450];
    __shared__ int   s_cnt[50], s_start[50], s_cur[50];
    __shared__ float s_dinv[50];
    __shared__ float s_pool[128];

    const int b = blockIdx.x, tid = threadIdx.x;
    const int* eb = ei + (size_t)b * 800;

    if (tid < 50)  s_cnt[tid] = 0;
    if (tid < 128) s_pool[tid] = 0.f;
    __syncthreads();

    for (int e = tid; e < 450; e += 256) {
        int dst = (e < 400) ? eb[400 + e] : (e - 400);
        atomicAdd(&s_cnt[dst], 1);
    }
    __syncthreads();

    if (tid < 50) s_dinv[tid] = rsqrtf((float)s_cnt[tid]);
    if (tid == 0) {
        int s = 0;
        for (int i = 0; i < 50; i++) { s_start[i] = s; s += s_cnt[i]; }
    }
    __syncthreads();
    if (tid < 50) s_cur[tid] = s_start[tid];
    __syncthreads();

    for (int e = tid; e < 450; e += 256) {
        int src, dst;
        if (e < 400) { src = eb[e]; dst = eb[400 + e]; }
        else         { src = dst = e - 400; }
        int pos = atomicAdd(&s_cur[dst], 1);
        s_src[pos]  = src;
        s_norm[pos] = s_dinv[src] * s_dinv[dst];
    }
    __syncthreads();

    const int f  = tid & 127;
    const int n0 = tid >> 7;
    const float* Hb = H + (size_t)b * 50 * 128;
    float pp = 0.f;
    for (int n = n0; n < 50; n += 2) {
        float acc = 0.f;
        int st = s_start[n], en = st + s_cnt[n];
        for (int j = st; j < en; j++)
            acc += s_norm[j] * Hb[s_src[j] * 128 + f];
        float v = lrelu(acc + bias[f]);
        if (Xout) Xout[(size_t)(b * 50 + n) * 128 + f] = __float2bfloat16(v);
        pp += v;
    }
    if (pooled) {
        atomicAdd(&s_pool[f], pp);
        __syncthreads();
        if (tid < 128) pooled[b * 128 + tid] = s_pool[tid] * (1.0f / 50.0f);
    }
}

// ---------------- head: FC1 -> FC2 -> cumsum (warp scan) -> sigmoid ----------------
__global__ __launch_bounds__(256) void head_kernel(
    const float* __restrict__ pooled,
    const float* __restrict__ Wf1, const float* __restrict__ bf1,
    const float* __restrict__ Wf2, const float* __restrict__ bf2,
    float* __restrict__ out)
{
    __shared__ float s_p[128];
    __shared__ float s_z1[64];
    __shared__ float s_z2[2000];

    const int b = blockIdx.x, tid = threadIdx.x;
    if (tid < 128) s_p[tid] = pooled[b * 128 + tid];
    __syncthreads();

    if (tid < 64) {
        float a = bf1[tid];
        #pragma unroll 8
        for (int k = 0; k < 128; k++) a += s_p[k] * Wf1[k * 64 + tid];
        s_z1[tid] = lrelu(a);
    }
    __syncthreads();

    for (int j = tid; j < 2000; j += 256) {
        float a = bf2[j];
        #pragma unroll
        for (int k = 0; k < 64; k++) a += s_z1[k] * Wf2[k * 2000 + j];
        s_z2[j] = a;
    }
    __syncthreads();

    if (tid < 64) {
        int c = tid >> 5, l = tid & 31;
        int k0 = l * 32, k1 = (k0 + 32 < 1000) ? k0 + 32 : 1000;
        float s = 0.f;
        for (int k = k0; k < k1; k++) s += s_z2[2 * k + c];
        float run = s;
        #pragma unroll
        for (int d = 1; d < 32; d <<= 1) {
            float v = __shfl_up_sync(0xffffffff, run, d);
            if (l >= d) run += v;
        }
        float a = run - s;
        float* ob = out + (size_t)b * 2000;
        for (int k = k0; k < k1; k++) {
            a += s_z2[2 * k + c];
            ob[2 * k + c] = 1.f / (1.f + expf(-a));
        }
    }
}

// ---------------- launch ----------------
extern "C" void kernel_launch(void* const* d_in, const int* in_sizes, int n_in,
                              void* d_out, int out_size)
{
    const float* bin = (const float*)d_in[0];
    const int*   ei  = (const int*)  d_in[1];
    const float* W1  = (const float*)d_in[2];
    const float* b1  = (const float*)d_in[3];
    const float* W2  = (const float*)d_in[4];
    const float* b2  = (const float*)d_in[5];
    const float* W3  = (const float*)d_in[6];
    const float* b3  = (const float*)d_in[7];
    const float* Wc1 = (const float*)d_in[8];
    const float* bc1 = (const float*)d_in[9];
    const float* Wc2 = (const float*)d_in[10];
    const float* bc2 = (const float*)d_in[11];
    const float* Wf1 = (const float*)d_in[12];
    const float* bf1 = (const float*)d_in[13];
    const float* Wf2 = (const float*)d_in[14];
    const float* bf2 = (const float*)d_in[15];
    float* out = (float*)d_out;

    float *P, *H, *PL;
    __nv_bfloat16 *Xin, *Xb1, *Xb2, *Xb3, *X2b;
    cudaGetSymbolAddress((void**)&P,   g_P);
    cudaGetSymbolAddress((void**)&Xin, g_Xin);
    cudaGetSymbolAddress((void**)&Xb1, g_Xb1);
    cudaGetSymbolAddress((void**)&Xb2, g_Xb2);
    cudaGetSymbolAddress((void**)&Xb3, g_Xb3);
    cudaGetSymbolAddress((void**)&X2b, g_X2b);
    cudaGetSymbolAddress((void**)&H,   g_H);
    cudaGetSymbolAddress((void**)&PL,  g_PL);

    cudaFuncSetAttribute(gemm_bf16, cudaFuncAttributeMaxDynamicSharedMemorySize,
                         GEMM_SMEM_BYTES);

    // prep: convert input to bf16
    prep_kernel<<<1600, 256>>>((const float4*)bin, (uint2*)Xin);

    // encoder L1: (64,25600)@(25600,3200); 12 K-chunks of 2176 -> 300 CTAs
    gemm_bf16<<<dim3(25, 12, 1), 256, GEMM_SMEM_BYTES>>>(Xin, W1, P, 25600, 3200, 2176, 0);
    reduce_act<<<200, 256>>>((const float4*)P, (const float4*)b1, (uint2*)Xb1, 800, 51200, 12, 1);

    // encoder L2: (64,3200)@(3200,6400); 6 K-chunks of 576 -> 300 CTAs
    gemm_bf16<<<dim3(50, 6, 1), 256, GEMM_SMEM_BYTES>>>(Xb1, W2, P, 3200, 6400, 576, 0);
    reduce_act<<<400, 256>>>((const float4*)P, (const float4*)b2, (uint2*)Xb2, 1600, 102400, 6, 1);

    // encoder L3 (no act): (64,6400)@(6400,12800); 3 K-chunks of 2176 -> 300 CTAs
    gemm_bf16<<<dim3(100, 3, 1), 256, GEMM_SMEM_BYTES>>>(Xb2, W3, P, 6400, 12800, 2176, 0);
    reduce_act<<<800, 256>>>((const float4*)P, (const float4*)b3, (uint2*)Xb3, 3200, 204800, 3, 0);

    // GCN L1: H = nodes(3200,256)@Wc1(256,128), direct store
    gemm_bf16<<<dim3(1, 1, 50), 256, GEMM_SMEM_BYTES>>>(Xb3, Wc1, H, 256, 128, 256, 1);
    gcn_agg<<<64, 256>>>(H, ei, bc1, X2b, nullptr);

    // GCN L2: H = X2(3200,128)@Wc2(128,128), direct store
    gemm_bf16<<<dim3(1, 1, 50), 256, GEMM_SMEM_BYTES>>>(X2b, Wc2, H, 128, 128, 128, 1);
    gcn_agg<<<64, 256>>>(H, ei, bc2, nullptr, PL);

    head_kernel<<<64, 256>>>(PL, Wf1, bf1, Wf2, bf2, out);
}